// round 4
// baseline (speedup 1.0000x reference)
#include <cuda_runtime.h>
#include <math_constants.h>
#include <cstdint>

#define D_MODEL  1024
#define ALPHA    0.5f
#define WINDOW   64          // 0.5^64 ~ 5e-20: truncation far below 1e-3 rel-err

// Scratch for per-token scores (1 MB). Device global: no allocation at launch.
#define MAX_TOKENS 262144
__device__ float g_scores[MAX_TOKENS];

// -------------------------------------------------------------------------
// Kernel 1: scores[row] = dot(x[row, :], W) + b   (memory-bound, ~1 GB read)
// Warp-per-row, W held in REGISTERS (row-invariant), 2 rows unrolled per
// iteration for 16 outstanding LDG.128 and overlap of reduce chain A with
// load stream B.
// -------------------------------------------------------------------------
__global__ __launch_bounds__(256)
void score_kernel(const float* __restrict__ x,
                  const float* __restrict__ W,
                  const float* __restrict__ b,
                  float* __restrict__ out,
                  int n_rows)
{
    const int tid  = threadIdx.x;
    const int warp = tid >> 5;
    const int lane = tid & 31;

    // Initialize output to -inf (d_out is poisoned to 0xAA before timing)
    if (blockIdx.x == 0 && tid == 0)
        *out = -CUDART_INF_F;

    // W into registers: lane covers columns {lane*4 + i*128 .. +3}, i=0..7.
    // L2/L1 resident broadcast across warps — one-time cost.
    float4 w[8];
    const float4* W4 = reinterpret_cast<const float4*>(W);
    #pragma unroll
    for (int i = 0; i < 8; i++)
        w[i] = __ldg(&W4[lane + i * 32]);

    const float bias = __ldg(b);
    const int gwarp  = blockIdx.x * 8 + warp;     // 8 warps/block
    const int nwarps = gridDim.x * 8;

    for (int row = gwarp; row < n_rows; row += 2 * nwarps) {
        const int row2 = row + nwarps;
        const float4* xa =
            reinterpret_cast<const float4*>(x + (size_t)row * D_MODEL);
        float acc_a = 0.f, acc_b = 0.f;

        if (row2 < n_rows) {
            const float4* xb =
                reinterpret_cast<const float4*>(x + (size_t)row2 * D_MODEL);
            #pragma unroll
            for (int i = 0; i < 8; i++) {          // 16 independent LDG.128
                float4 av = xa[lane + i * 32];
                float4 bv = xb[lane + i * 32];
                acc_a = fmaf(av.x, w[i].x, acc_a);
                acc_a = fmaf(av.y, w[i].y, acc_a);
                acc_a = fmaf(av.z, w[i].z, acc_a);
                acc_a = fmaf(av.w, w[i].w, acc_a);
                acc_b = fmaf(bv.x, w[i].x, acc_b);
                acc_b = fmaf(bv.y, w[i].y, acc_b);
                acc_b = fmaf(bv.z, w[i].z, acc_b);
                acc_b = fmaf(bv.w, w[i].w, acc_b);
            }
            #pragma unroll
            for (int o = 16; o; o >>= 1) {
                acc_a += __shfl_xor_sync(0xffffffffu, acc_a, o);
                acc_b += __shfl_xor_sync(0xffffffffu, acc_b, o);
            }
            if (lane == 0) {
                g_scores[row]  = acc_a + bias;
                g_scores[row2] = acc_b + bias;
            }
        } else {
            #pragma unroll
            for (int i = 0; i < 8; i++) {
                float4 av = xa[lane + i * 32];
                acc_a = fmaf(av.x, w[i].x, acc_a);
                acc_a = fmaf(av.y, w[i].y, acc_a);
                acc_a = fmaf(av.z, w[i].z, acc_a);
                acc_a = fmaf(av.w, w[i].w, acc_a);
            }
            #pragma unroll
            for (int o = 16; o; o >>= 1)
                acc_a += __shfl_xor_sync(0xffffffffu, acc_a, o);
            if (lane == 0)
                g_scores[row] = acc_a + bias;
        }
    }
}

// -------------------------------------------------------------------------
// Kernel 2: windowed EMA + global max.
// Each block covers 1024 tokens (+64 halo in smem). Each thread handles 4
// CONSECUTIVE tokens: 64-tap window seeds the first, then the exact
// recurrence e = 0.5*s + 0.5*e produces the rest (1 FMA each).
// -------------------------------------------------------------------------
__device__ __forceinline__ void atomic_max_float(float* addr, float val)
{
    if (val >= 0.f)
        atomicMax(reinterpret_cast<int*>(addr), __float_as_int(val));
    else
        atomicMin(reinterpret_cast<unsigned int*>(addr), __float_as_uint(val));
}

#define CHUNK 1024

__global__ __launch_bounds__(256)
void ema_max_kernel(float* __restrict__ out, int n)
{
    __shared__ float s[CHUNK + WINDOW];
    __shared__ float wmax[8];

    const int tid  = threadIdx.x;
    const int base = blockIdx.x * CHUNK;

    // Load halo + chunk as float4 (272 vectors). base-WINDOW is 4-aligned.
    #pragma unroll
    for (int i = tid; i < (CHUNK + WINDOW) / 4; i += 256) {
        const int g4 = (base - WINDOW) / 4 + i;   // float4 index into g_scores
        const int g0 = g4 * 4;
        float4 v;
        if (g0 >= 0 && g0 + 3 < n) {
            v = reinterpret_cast<const float4*>(g_scores)[g4];
        } else {
            v.x = (g0 + 0 >= 0 && g0 + 0 < n) ? g_scores[g0 + 0] : 0.f;
            v.y = (g0 + 1 >= 0 && g0 + 1 < n) ? g_scores[g0 + 1] : 0.f;
            v.z = (g0 + 2 >= 0 && g0 + 2 < n) ? g_scores[g0 + 2] : 0.f;
            v.w = (g0 + 3 >= 0 && g0 + 3 < n) ? g_scores[g0 + 3] : 0.f;
        }
        *reinterpret_cast<float4*>(&s[i * 4]) = v;
    }
    __syncthreads();

    const int p = tid * 4;                 // local position of this thread's 1st token

    // Seed: 64-tap windowed EMA for token base+p (coeffs fold to immediates).
    float e = 0.f, wc = ALPHA;
    #pragma unroll
    for (int k = 0; k < WINDOW; k++) {
        e = fmaf(wc, s[WINDOW + p - k], e);
        wc *= (1.0f - ALPHA);
    }
    float m = (base + p < n) ? e : -CUDART_INF_F;

    // Exact recurrence for the next 3 tokens.
    #pragma unroll
    for (int j = 1; j < 4; j++) {
        e = fmaf(ALPHA, s[WINDOW + p + j], (1.0f - ALPHA) * e);
        if (base + p + j < n) m = fmaxf(m, e);
    }

    // Block max reduction
    #pragma unroll
    for (int o = 16; o; o >>= 1)
        m = fmaxf(m, __shfl_xor_sync(0xffffffffu, m, o));
    if ((tid & 31) == 0) wmax[tid >> 5] = m;
    __syncthreads();
    if (tid < 8) {
        float r = wmax[tid];
        #pragma unroll
        for (int o = 4; o; o >>= 1)
            r = fmaxf(r, __shfl_xor_sync(0xffu, r, o));
        if (tid == 0)
            atomic_max_float(out, r);
    }
}

// -------------------------------------------------------------------------
extern "C" void kernel_launch(void* const* d_in, const int* in_sizes, int n_in,
                              void* d_out, int out_size)
{
    const float* x = (const float*)d_in[0];
    const float* W = (const float*)d_in[1];
    const float* b = (const float*)d_in[2];
    float* out     = (float*)d_out;

    const int n = in_sizes[0] / D_MODEL;    // 262144

    // 8 warps/block, 4 rows/warp (2 unrolled pairs) per grid-stride
    const int grid1 = (n + 8 * 4 - 1) / (8 * 4);      // 8192 blocks
    score_kernel<<<grid1, 256>>>(x, W, b, out, n);

    const int grid2 = (n + CHUNK - 1) / CHUNK;         // 256 blocks
    ema_max_kernel<<<grid2, 256>>>(out, n);
}

// round 6
// speedup vs baseline: 1.0299x; 1.0299x over previous
#include <cuda_runtime.h>
#include <math_constants.h>
#include <cstdint>

#define D_MODEL  1024
#define ALPHA    0.5f
#define WINDOW   64          // 0.5^64 ~ 5e-20: truncation far below 1e-3 rel-err

// Scratch for per-token scores (1 MB). Device global: no allocation at launch.
#define MAX_TOKENS 262144
__device__ float g_scores[MAX_TOKENS];

// -------------------------------------------------------------------------
// Kernel 1: scores[row] = dot(x[row, :], W) + b   (memory-bound, ~1 GB read)
// One warp per row, single pass (no grid-stride loop). 8 front-batched
// LDG.128 per thread with streaming hint (read-once data, keep L2 for
// g_scores). W held in registers (broadcast, L1-resident after warp 0).
// -------------------------------------------------------------------------
__global__ __launch_bounds__(256)
void score_kernel(const float* __restrict__ x,
                  const float* __restrict__ W,
                  const float* __restrict__ b,
                  float* __restrict__ out,
                  int n_rows)
{
    const int tid  = threadIdx.x;
    const int warp = tid >> 5;
    const int lane = tid & 31;

    // Initialize output to -inf (d_out is poisoned to 0xAA before timing)
    if (blockIdx.x == 0 && tid == 0)
        *out = -CUDART_INF_F;

    const int row = blockIdx.x * 8 + warp;       // 8 warps/block, 1 row each
    if (row >= n_rows) return;

    // W into registers: lane covers columns {lane*4 + i*128 .. +3}, i=0..7.
    float4 w[8];
    const float4* W4 = reinterpret_cast<const float4*>(W);
    #pragma unroll
    for (int i = 0; i < 8; i++)
        w[i] = __ldg(&W4[lane + i * 32]);

    const float4* xr = reinterpret_cast<const float4*>(x + (size_t)row * D_MODEL);

    // Front-batch 8 independent streaming LDG.128 (MLP=8/thread)
    float4 xv[8];
    #pragma unroll
    for (int i = 0; i < 8; i++)
        xv[i] = __ldcs(&xr[lane + i * 32]);

    float acc = 0.f;
    #pragma unroll
    for (int i = 0; i < 8; i++) {
        acc = fmaf(xv[i].x, w[i].x, acc);
        acc = fmaf(xv[i].y, w[i].y, acc);
        acc = fmaf(xv[i].z, w[i].z, acc);
        acc = fmaf(xv[i].w, w[i].w, acc);
    }
    #pragma unroll
    for (int o = 16; o; o >>= 1)
        acc += __shfl_xor_sync(0xffffffffu, acc, o);

    if (lane == 0)
        g_scores[row] = acc + __ldg(b);
}

// -------------------------------------------------------------------------
// Kernel 2: windowed EMA + global max.
// Each block covers 2048 tokens (+64 halo in smem). Each thread handles 8
// CONSECUTIVE tokens: 64-tap window seeds the first, then the exact
// recurrence e = 0.5*s + 0.5*e produces the rest (1 FMA each).
// -------------------------------------------------------------------------
__device__ __forceinline__ void atomic_max_float(float* addr, float val)
{
    if (val >= 0.f)
        atomicMax(reinterpret_cast<int*>(addr), __float_as_int(val));
    else
        atomicMin(reinterpret_cast<unsigned int*>(addr), __float_as_uint(val));
}

#define CHUNK 2048

__global__ __launch_bounds__(256)
void ema_max_kernel(float* __restrict__ out, int n)
{
    __shared__ float s[CHUNK + WINDOW];
    __shared__ float wmax[8];

    const int tid  = threadIdx.x;
    const int base = blockIdx.x * CHUNK;

    // Load halo + chunk as float4 (528 vectors). base-WINDOW is 4-aligned.
    #pragma unroll
    for (int i = tid; i < (CHUNK + WINDOW) / 4; i += 256) {
        const int g4 = (base - WINDOW) / 4 + i;   // float4 index into g_scores
        const int g0 = g4 * 4;
        float4 v;
        if (g0 >= 0 && g0 + 3 < n) {
            v = reinterpret_cast<const float4*>(g_scores)[g4];
        } else {
            v.x = (g0 + 0 >= 0 && g0 + 0 < n) ? g_scores[g0 + 0] : 0.f;
            v.y = (g0 + 1 >= 0 && g0 + 1 < n) ? g_scores[g0 + 1] : 0.f;
            v.z = (g0 + 2 >= 0 && g0 + 2 < n) ? g_scores[g0 + 2] : 0.f;
            v.w = (g0 + 3 >= 0 && g0 + 3 < n) ? g_scores[g0 + 3] : 0.f;
        }
        *reinterpret_cast<float4*>(&s[i * 4]) = v;
    }
    __syncthreads();

    const int p = tid * 8;                 // local position of this thread's 1st token

    // Seed: 64-tap windowed EMA for token base+p (coeffs fold to immediates).
    float e = 0.f, wc = ALPHA;
    #pragma unroll
    for (int k = 0; k < WINDOW; k++) {
        e = fmaf(wc, s[WINDOW + p - k], e);
        wc *= (1.0f - ALPHA);
    }
    float m = (base + p < n) ? e : -CUDART_INF_F;

    // Exact recurrence for the next 7 tokens.
    #pragma unroll
    for (int j = 1; j < 8; j++) {
        e = fmaf(ALPHA, s[WINDOW + p + j], (1.0f - ALPHA) * e);
        if (base + p + j < n) m = fmaxf(m, e);
    }

    // Block max reduction
    #pragma unroll
    for (int o = 16; o; o >>= 1)
        m = fmaxf(m, __shfl_xor_sync(0xffffffffu, m, o));
    if ((tid & 31) == 0) wmax[tid >> 5] = m;
    __syncthreads();
    if (tid < 8) {
        float r = wmax[tid];
        #pragma unroll
        for (int o = 4; o; o >>= 1)
            r = fmaxf(r, __shfl_xor_sync(0xffu, r, o));
        if (tid == 0)
            atomic_max_float(out, r);
    }
}

// -------------------------------------------------------------------------
extern "C" void kernel_launch(void* const* d_in, const int* in_sizes, int n_in,
                              void* d_out, int out_size)
{
    const float* x = (const float*)d_in[0];
    const float* W = (const float*)d_in[1];
    const float* b = (const float*)d_in[2];
    float* out     = (float*)d_out;

    const int n = in_sizes[0] / D_MODEL;    // 262144

    const int grid1 = (n + 7) / 8;                     // 32768 blocks, 1 row/warp
    score_kernel<<<grid1, 256>>>(x, W, b, out, n);

    const int grid2 = (n + CHUNK - 1) / CHUNK;         // 128 blocks
    ema_max_kernel<<<grid2, 256>>>(out, n);
}